// round 2
// baseline (speedup 1.0000x reference)
#include <cuda_runtime.h>

#define DIM   768
#define HS    64
#define NSEQ  4096
#define BATCH 4
#define MROWS (BATCH * NSEQ)   // 16384

// Scratch for projected q, k, v (4 MB each). Device globals (no allocation).
__device__ float g_q[MROWS * HS];
__device__ float g_k[MROWS * HS];
__device__ float g_v[MROWS * HS];

// ---------------------------------------------------------------------------
// Kernel 1: QKV projection.  out[m][h] = sum_d ix[m][d] * W[d][h]
// M = 16384, K = 768, N = 64 per weight.  grid = (256, 3), 256 threads.
// Tiles: BM=64, BN=64 (full head), BK=32.  4x4 micro-tile per thread.
// ---------------------------------------------------------------------------
#define PBM 64
#define PBK 32
#define PASTR (PBK + 4)   // 36 floats: float4-aligned, dodges bank conflicts

__global__ __launch_bounds__(256) void proj_kernel(
    const float* __restrict__ ix,
    const float* __restrict__ Wk,
    const float* __restrict__ Wq,
    const float* __restrict__ Wv)
{
    __shared__ float sA[PBM * PASTR];
    __shared__ float sB[PBK * HS];

    const float* W;
    float* outp;
    if (blockIdx.y == 0)      { W = Wq; outp = g_q; }
    else if (blockIdx.y == 1) { W = Wk; outp = g_k; }
    else                      { W = Wv; outp = g_v; }

    const int m0  = blockIdx.x * PBM;
    const int tid = threadIdx.x;
    const int ty  = tid >> 4;
    const int tx  = tid & 15;

    float acc[4][4] = {};

    for (int k0 = 0; k0 < DIM; k0 += PBK) {
        // Load A tile: 64 x 32 floats = 512 float4, 2 per thread, coalesced.
        #pragma unroll
        for (int f = tid; f < PBM * PBK / 4; f += 256) {
            int row = f >> 3;        // 8 float4 per row
            int cg  = f & 7;
            float4 v = *(const float4*)(ix + (size_t)(m0 + row) * DIM + k0 + cg * 4);
            *(float4*)&sA[row * PASTR + cg * 4] = v;
        }
        // Load B tile: 32 x 64 floats = 512 float4.
        #pragma unroll
        for (int f = tid; f < PBK * HS / 4; f += 256) {
            int row = f >> 4;        // 16 float4 per row
            int cg  = f & 15;
            *(float4*)&sB[row * HS + cg * 4] =
                *(const float4*)(W + (size_t)(k0 + row) * HS + cg * 4);
        }
        __syncthreads();

        #pragma unroll
        for (int k = 0; k < PBK; ++k) {
            float a0 = sA[(ty * 4 + 0) * PASTR + k];
            float a1 = sA[(ty * 4 + 1) * PASTR + k];
            float a2 = sA[(ty * 4 + 2) * PASTR + k];
            float a3 = sA[(ty * 4 + 3) * PASTR + k];
            float4 b = *(float4*)&sB[k * HS + tx * 4];
            acc[0][0] += a0 * b.x; acc[0][1] += a0 * b.y; acc[0][2] += a0 * b.z; acc[0][3] += a0 * b.w;
            acc[1][0] += a1 * b.x; acc[1][1] += a1 * b.y; acc[1][2] += a1 * b.z; acc[1][3] += a1 * b.w;
            acc[2][0] += a2 * b.x; acc[2][1] += a2 * b.y; acc[2][2] += a2 * b.z; acc[2][3] += a2 * b.w;
            acc[3][0] += a3 * b.x; acc[3][1] += a3 * b.y; acc[3][2] += a3 * b.z; acc[3][3] += a3 * b.w;
        }
        __syncthreads();
    }

    #pragma unroll
    for (int i = 0; i < 4; ++i) {
        float4 r = make_float4(acc[i][0], acc[i][1], acc[i][2], acc[i][3]);
        *(float4*)(outp + (size_t)(m0 + ty * 4 + i) * HS + tx * 4) = r;
    }
}

// ---------------------------------------------------------------------------
// Kernel 2: flash attention.  One block = 64 query rows of one batch.
// Streams 64-row K/V tiles through SMEM with online softmax.
// 256 threads, 16x16 thread grid, 4x4 micro-tiles for S and for P@V.
// ---------------------------------------------------------------------------
#define FBM 64
#define FBN 64
#define FSTR 68    // padded row stride (float4-aligned, conflict-free broadcast)

__global__ __launch_bounds__(256) void flash_kernel(float* __restrict__ outp)
{
    extern __shared__ float sm[];
    float* sQ = sm;                  // [64][68]
    float* sK = sQ + FBM * FSTR;     // [64][68]
    float* sV = sK + FBN * FSTR;     // [64][68]
    float* sP = sV + FBN * FSTR;     // [64][68]

    const int bx = blockIdx.x;
    const int b  = bx >> 6;          // 64 q-tiles per batch
    const int qt = bx & 63;

    const float* Qg = g_q + ((size_t)b * NSEQ + qt * FBM) * HS;
    const float* Kg = g_k + (size_t)b * NSEQ * HS;
    const float* Vg = g_v + (size_t)b * NSEQ * HS;

    const int tid = threadIdx.x;
    const int ty  = tid >> 4;
    const int tx  = tid & 15;
    const float scale = 0.125f;      // HS^-0.5

    // Load Q tile, pre-scaled.
    #pragma unroll
    for (int f = tid; f < FBM * HS / 4; f += 256) {
        int row = f >> 4, cg = f & 15;
        float4 v = *(const float4*)(Qg + (size_t)row * HS + cg * 4);
        v.x *= scale; v.y *= scale; v.z *= scale; v.w *= scale;
        *(float4*)&sQ[row * FSTR + cg * 4] = v;
    }

    float m_i[4], l_i[4], accO[4][4] = {};
    #pragma unroll
    for (int i = 0; i < 4; ++i) { m_i[i] = -1e30f; l_i[i] = 0.0f; }

    for (int kt = 0; kt < NSEQ / FBN; ++kt) {
        __syncthreads();   // prev iteration's reads of sK/sV/sP complete
        #pragma unroll
        for (int f = tid; f < FBN * HS / 4; f += 256) {
            int row = f >> 4, cg = f & 15;
            *(float4*)&sK[row * FSTR + cg * 4] =
                *(const float4*)(Kg + (size_t)(kt * FBN + row) * HS + cg * 4);
            *(float4*)&sV[row * FSTR + cg * 4] =
                *(const float4*)(Vg + (size_t)(kt * FBN + row) * HS + cg * 4);
        }
        __syncthreads();

        // S[i][j] = q_row(ty*4+i) . k_row(tx*4+j)   (float4 over k)
        float s[4][4] = {};
        #pragma unroll
        for (int k = 0; k < HS; k += 4) {
            float4 qa[4], kb[4];
            #pragma unroll
            for (int i = 0; i < 4; ++i) qa[i] = *(float4*)&sQ[(ty * 4 + i) * FSTR + k];
            #pragma unroll
            for (int j = 0; j < 4; ++j) kb[j] = *(float4*)&sK[(tx * 4 + j) * FSTR + k];
            #pragma unroll
            for (int i = 0; i < 4; ++i)
                #pragma unroll
                for (int j = 0; j < 4; ++j)
                    s[i][j] += qa[i].x * kb[j].x + qa[i].y * kb[j].y
                             + qa[i].z * kb[j].z + qa[i].w * kb[j].w;
        }

        // Online softmax per row (row shared by the 16 tx lanes of one ty group).
        #pragma unroll
        for (int i = 0; i < 4; ++i) {
            float mx = fmaxf(fmaxf(s[i][0], s[i][1]), fmaxf(s[i][2], s[i][3]));
            #pragma unroll
            for (int o = 8; o >= 1; o >>= 1)
                mx = fmaxf(mx, __shfl_xor_sync(0xffffffffu, mx, o));
            float m_new = fmaxf(m_i[i], mx);
            float alpha = __expf(m_i[i] - m_new);
            float rs = 0.0f;
            #pragma unroll
            for (int j = 0; j < 4; ++j) { s[i][j] = __expf(s[i][j] - m_new); rs += s[i][j]; }
            #pragma unroll
            for (int o = 8; o >= 1; o >>= 1)
                rs += __shfl_xor_sync(0xffffffffu, rs, o);
            l_i[i] = l_i[i] * alpha + rs;
            m_i[i] = m_new;
            #pragma unroll
            for (int j = 0; j < 4; ++j) accO[i][j] *= alpha;
        }

        // Stage P to SMEM for the P@V GEMM.
        #pragma unroll
        for (int i = 0; i < 4; ++i)
            #pragma unroll
            for (int j = 0; j < 4; ++j)
                sP[(ty * 4 + i) * FSTR + tx * 4 + j] = s[i][j];
        __syncthreads();

        // O += P @ V
        #pragma unroll 16
        for (int j = 0; j < FBN; ++j) {
            float4 vv = *(float4*)&sV[j * FSTR + tx * 4];
            float p0 = sP[(ty * 4 + 0) * FSTR + j];
            float p1 = sP[(ty * 4 + 1) * FSTR + j];
            float p2 = sP[(ty * 4 + 2) * FSTR + j];
            float p3 = sP[(ty * 4 + 3) * FSTR + j];
            accO[0][0] += p0 * vv.x; accO[0][1] += p0 * vv.y; accO[0][2] += p0 * vv.z; accO[0][3] += p0 * vv.w;
            accO[1][0] += p1 * vv.x; accO[1][1] += p1 * vv.y; accO[1][2] += p1 * vv.z; accO[1][3] += p1 * vv.w;
            accO[2][0] += p2 * vv.x; accO[2][1] += p2 * vv.y; accO[2][2] += p2 * vv.z; accO[2][3] += p2 * vv.w;
            accO[3][0] += p3 * vv.x; accO[3][1] += p3 * vv.y; accO[3][2] += p3 * vv.z; accO[3][3] += p3 * vv.w;
        }
    }

    float* Og = outp + ((size_t)b * NSEQ + qt * FBM) * HS;
    #pragma unroll
    for (int i = 0; i < 4; ++i) {
        float inv = 1.0f / l_i[i];
        float4 r = make_float4(accO[i][0] * inv, accO[i][1] * inv,
                               accO[i][2] * inv, accO[i][3] * inv);
        *(float4*)(Og + (size_t)(ty * 4 + i) * HS + tx * 4) = r;
    }
}

// ---------------------------------------------------------------------------
// Launch
// ---------------------------------------------------------------------------
extern "C" void kernel_launch(void* const* d_in, const int* in_sizes, int n_in,
                              void* d_out, int out_size)
{
    (void)in_sizes; (void)n_in; (void)out_size;
    const float* ix = (const float*)d_in[0];
    const float* Wk = (const float*)d_in[1];
    const float* Wq = (const float*)d_in[2];
    const float* Wv = (const float*)d_in[3];
    float* out = (float*)d_out;

    const int smem_bytes = 4 * FBM * FSTR * (int)sizeof(float);  // 69632
    cudaFuncSetAttribute(flash_kernel,
                         cudaFuncAttributeMaxDynamicSharedMemorySize, smem_bytes);

    dim3 pgrid(MROWS / PBM, 3);          // (256, 3)
    proj_kernel<<<pgrid, 256>>>(ix, Wk, Wq, Wv);

    flash_kernel<<<BATCH * (NSEQ / FBM), 256, smem_bytes>>>(out);  // 256 blocks
}

// round 3
// speedup vs baseline: 1.6981x; 1.6981x over previous
#include <cuda_runtime.h>

#define DIM   768
#define HS    64
#define NSEQ  4096
#define BATCH 4
#define MROWS (BATCH * NSEQ)

typedef unsigned long long u64;

__device__ float g_q[MROWS * HS];
__device__ float g_k[MROWS * HS];
__device__ float g_v[MROWS * HS];

__device__ __forceinline__ u64 pack2(float lo, float hi) {
    u64 r; asm("mov.b64 %0, {%1, %2};" : "=l"(r) : "f"(lo), "f"(hi)); return r;
}
__device__ __forceinline__ u64 dup2(float x) {
    u64 r; asm("mov.b64 %0, {%1, %1};" : "=l"(r) : "f"(x)); return r;
}
__device__ __forceinline__ void unpack2(u64 v, float& lo, float& hi) {
    asm("mov.b64 {%0, %1}, %2;" : "=f"(lo), "=f"(hi) : "l"(v));
}
__device__ __forceinline__ u64 fma2(u64 a, u64 b, u64 c) {
    u64 d; asm("fma.rn.f32x2 %0, %1, %2, %3;" : "=l"(d) : "l"(a), "l"(b), "l"(c)); return d;
}
__device__ __forceinline__ u64 mul2(u64 a, u64 b) {
    u64 d; asm("mul.rn.f32x2 %0, %1, %2;" : "=l"(d) : "l"(a), "l"(b)); return d;
}

// ---------- Kernel 1: QKV projection, f32x2, A transposed in SMEM ----------
#define PBM 64
#define PBK 32
#define SAT 68

__global__ __launch_bounds__(256) void proj_kernel(
    const float* __restrict__ ix, const float* __restrict__ Wk,
    const float* __restrict__ Wq, const float* __restrict__ Wv)
{
    __shared__ float sAT[PBK * SAT];   // [k][row]
    __shared__ float sB[PBK * HS];

    const float* W; float* outp;
    if (blockIdx.y == 0)      { W = Wq; outp = g_q; }
    else if (blockIdx.y == 1) { W = Wk; outp = g_k; }
    else                      { W = Wv; outp = g_v; }

    const int m0 = blockIdx.x * PBM, tid = threadIdx.x;
    const int ty = tid >> 4, tx = tid & 15;
    u64 acc[2][4] = {};

    for (int k0 = 0; k0 < DIM; k0 += PBK) {
        #pragma unroll
        for (int f = tid; f < PBM * PBK / 4; f += 256) {
            int row = f >> 3, kg = f & 7;
            float4 a = *(const float4*)(ix + (size_t)(m0 + row) * DIM + k0 + kg * 4);
            sAT[(4 * kg + 0) * SAT + row] = a.x;
            sAT[(4 * kg + 1) * SAT + row] = a.y;
            sAT[(4 * kg + 2) * SAT + row] = a.z;
            sAT[(4 * kg + 3) * SAT + row] = a.w;
        }
        #pragma unroll
        for (int f = tid; f < PBK * HS / 4; f += 256) {
            int row = f >> 4, hg = f & 15;
            *(float4*)&sB[row * HS + hg * 4] =
                *(const float4*)(W + (size_t)(k0 + row) * HS + hg * 4);
        }
        __syncthreads();
        #pragma unroll
        for (int k = 0; k < PBK; ++k) {
            ulonglong2 a = *(const ulonglong2*)&sAT[k * SAT + ty * 4];
            float4 b = *(const float4*)&sB[k * HS + tx * 4];
            u64 b0 = dup2(b.x), b1 = dup2(b.y), b2 = dup2(b.z), b3 = dup2(b.w);
            acc[0][0] = fma2(a.x, b0, acc[0][0]); acc[0][1] = fma2(a.x, b1, acc[0][1]);
            acc[0][2] = fma2(a.x, b2, acc[0][2]); acc[0][3] = fma2(a.x, b3, acc[0][3]);
            acc[1][0] = fma2(a.y, b0, acc[1][0]); acc[1][1] = fma2(a.y, b1, acc[1][1]);
            acc[1][2] = fma2(a.y, b2, acc[1][2]); acc[1][3] = fma2(a.y, b3, acc[1][3]);
        }
        __syncthreads();
    }
    #pragma unroll
    for (int i2 = 0; i2 < 2; ++i2) {
        float lo[4], hi[4];
        #pragma unroll
        for (int c = 0; c < 4; ++c) unpack2(acc[i2][c], lo[c], hi[c]);
        *(float4*)(outp + (size_t)(m0 + ty * 4 + 2 * i2) * HS + tx * 4) =
            make_float4(lo[0], lo[1], lo[2], lo[3]);
        *(float4*)(outp + (size_t)(m0 + ty * 4 + 2 * i2 + 1) * HS + tx * 4) =
            make_float4(hi[0], hi[1], hi[2], hi[3]);
    }
}

// ---------- Kernel 2: flash attention, f32x2, 8x8 micro-tiles, 128 thr ----------
#define FBM 64
#define FBN 64
#define SQT 68
#define SKV 68
#define SPT 66

__global__ __launch_bounds__(128) void flash_kernel(float* __restrict__ outp)
{
    extern __shared__ float sm[];
    float* sQT = sm;               // [64 h][68 row]
    float* sK  = sQT + HS * SQT;   // [64 key][68 h]
    float* sV  = sK + FBN * SKV;
    float* sPT = sV + FBN * SKV;   // [64 key][66 row] packed pairs

    const int bx = blockIdx.x, b = bx >> 6, qt = bx & 63;
    const float* Qg = g_q + ((size_t)b * NSEQ + qt * FBM) * HS;
    const float* Kg = g_k + (size_t)b * NSEQ * HS;
    const float* Vg = g_v + (size_t)b * NSEQ * HS;

    const int tid = threadIdx.x;
    const int ty = tid >> 4, tx = tid & 15;
    const int cg = tid & 7, jh = (tid >> 3) & 1;

    for (int f = tid; f < FBM * HS / 4; f += 128) {
        int r = f >> 4, hg = f & 15;
        float4 q = *(const float4*)(Qg + (size_t)r * HS + hg * 4);
        sQT[(4 * hg + 0) * SQT + r] = q.x * 0.125f;
        sQT[(4 * hg + 1) * SQT + r] = q.y * 0.125f;
        sQT[(4 * hg + 2) * SQT + r] = q.z * 0.125f;
        sQT[(4 * hg + 3) * SQT + r] = q.w * 0.125f;
    }

    float m_i[8], l_i[8];
    #pragma unroll
    for (int i = 0; i < 8; ++i) { m_i[i] = -1e30f; l_i[i] = 0.0f; }
    u64 o2[4][8] = {};

    for (int kt = 0; kt < NSEQ / FBN; ++kt) {
        __syncthreads();
        const float* Kt = Kg + (size_t)kt * FBN * HS;
        const float* Vt = Vg + (size_t)kt * FBN * HS;
        #pragma unroll
        for (int f = tid; f < FBN * HS / 4; f += 128) {
            int row = f >> 4, hg = f & 15;
            *(float4*)&sK[row * SKV + hg * 4] = *(const float4*)(Kt + (size_t)row * HS + hg * 4);
            *(float4*)&sV[row * SKV + hg * 4] = *(const float4*)(Vt + (size_t)row * HS + hg * 4);
        }
        __syncthreads();

        // S = Q K^T : rows ty*8..+7 (4 pairs), cols tx+16*jj
        u64 s2[4][4] = {};
        #pragma unroll
        for (int h = 0; h < HS; h += 2) {
            ulonglong2 qa0 = *(const ulonglong2*)&sQT[h * SQT + ty * 8];
            ulonglong2 qa1 = *(const ulonglong2*)&sQT[h * SQT + ty * 8 + 4];
            ulonglong2 qb0 = *(const ulonglong2*)&sQT[(h + 1) * SQT + ty * 8];
            ulonglong2 qb1 = *(const ulonglong2*)&sQT[(h + 1) * SQT + ty * 8 + 4];
            u64 qA[4] = {qa0.x, qa0.y, qa1.x, qa1.y};
            u64 qB[4] = {qb0.x, qb0.y, qb1.x, qb1.y};
            #pragma unroll
            for (int jj = 0; jj < 4; ++jj) {
                u64 kk = *(const u64*)&sK[(tx + 16 * jj) * SKV + h];
                float k0, k1; unpack2(kk, k0, k1);
                u64 kd0 = dup2(k0), kd1 = dup2(k1);
                #pragma unroll
                for (int i2 = 0; i2 < 4; ++i2) {
                    s2[i2][jj] = fma2(qA[i2], kd0, s2[i2][jj]);
                    s2[i2][jj] = fma2(qB[i2], kd1, s2[i2][jj]);
                }
            }
        }

        // online softmax; rows shared by the 16 tx lanes of a ty group
        #pragma unroll
        for (int i2 = 0; i2 < 4; ++i2) {
            float a[4], bb[4];
            #pragma unroll
            for (int jj = 0; jj < 4; ++jj) unpack2(s2[i2][jj], a[jj], bb[jj]);
            float mxa = fmaxf(fmaxf(a[0], a[1]), fmaxf(a[2], a[3]));
            float mxb = fmaxf(fmaxf(bb[0], bb[1]), fmaxf(bb[2], bb[3]));
            #pragma unroll
            for (int o = 8; o >= 1; o >>= 1) {
                mxa = fmaxf(mxa, __shfl_xor_sync(0xffffffffu, mxa, o));
                mxb = fmaxf(mxb, __shfl_xor_sync(0xffffffffu, mxb, o));
            }
            const int ra = 2 * i2, rb = 2 * i2 + 1;
            float mna = fmaxf(m_i[ra], mxa), mnb = fmaxf(m_i[rb], mxb);
            float ala = __expf(m_i[ra] - mna), alb = __expf(m_i[rb] - mnb);
            float sa = 0.0f, sb = 0.0f;
            #pragma unroll
            for (int jj = 0; jj < 4; ++jj) {
                a[jj]  = __expf(a[jj]  - mna); sa += a[jj];
                bb[jj] = __expf(bb[jj] - mnb); sb += bb[jj];
            }
            #pragma unroll
            for (int o = 8; o >= 1; o >>= 1) {
                sa += __shfl_xor_sync(0xffffffffu, sa, o);
                sb += __shfl_xor_sync(0xffffffffu, sb, o);
            }
            l_i[ra] = l_i[ra] * ala + sa; m_i[ra] = mna;
            l_i[rb] = l_i[rb] * alb + sb; m_i[rb] = mnb;
            u64 al2 = pack2(ala, alb);
            #pragma unroll
            for (int c8 = 0; c8 < 8; ++c8) o2[i2][c8] = mul2(o2[i2][c8], al2);
            #pragma unroll
            for (int jj = 0; jj < 4; ++jj)
                *(u64*)&sPT[(tx + 16 * jj) * SPT + ty * 8 + 2 * i2] = pack2(a[jj], bb[jj]);
        }
        __syncthreads();

        // O += P V : this thread covers keys j ≡ jh (mod 2), h cols cg*8..+7
        #pragma unroll 2
        for (int jj = 0; jj < FBN / 2; ++jj) {
            int j = jj * 2 + jh;
            u64 p2[4];
            #pragma unroll
            for (int i2 = 0; i2 < 4; ++i2)
                p2[i2] = *(const u64*)&sPT[j * SPT + ty * 8 + 2 * i2];
            ulonglong2 v01 = *(const ulonglong2*)&sV[j * SKV + cg * 8];
            ulonglong2 v23 = *(const ulonglong2*)&sV[j * SKV + cg * 8 + 4];
            float v[8];
            unpack2(v01.x, v[0], v[1]); unpack2(v01.y, v[2], v[3]);
            unpack2(v23.x, v[4], v[5]); unpack2(v23.y, v[6], v[7]);
            #pragma unroll
            for (int c8 = 0; c8 < 8; ++c8) {
                u64 vd = dup2(v[c8]);
                #pragma unroll
                for (int i2 = 0; i2 < 4; ++i2)
                    o2[i2][c8] = fma2(p2[i2], vd, o2[i2][c8]);
            }
        }
    }

    // merge jh halves via SMEM, normalize, write
    __syncthreads();
    float* buf = sK;
    if (jh == 1) {
        int slot = (ty * 8 + cg) * 64;
        #pragma unroll
        for (int i2 = 0; i2 < 4; ++i2)
            #pragma unroll
            for (int c8 = 0; c8 < 8; ++c8)
                *(u64*)&buf[slot + (i2 * 8 + c8) * 2] = o2[i2][c8];
    }
    __syncthreads();
    if (jh == 0) {
        int slot = (ty * 8 + cg) * 64;
        float* Og = outp + ((size_t)b * NSEQ + qt * FBM) * HS;
        #pragma unroll
        for (int i2 = 0; i2 < 4; ++i2) {
            float il0 = 1.0f / l_i[2 * i2], il1 = 1.0f / l_i[2 * i2 + 1];
            float rlo[8], rhi[8];
            #pragma unroll
            for (int c8 = 0; c8 < 8; ++c8) {
                float x, y, p, q;
                unpack2(o2[i2][c8], x, y);
                unpack2(*(const u64*)&buf[slot + (i2 * 8 + c8) * 2], p, q);
                rlo[c8] = (x + p) * il0;
                rhi[c8] = (y + q) * il1;
            }
            int r0 = ty * 8 + 2 * i2;
            *(float4*)(Og + (size_t)r0 * HS + cg * 8)           = make_float4(rlo[0], rlo[1], rlo[2], rlo[3]);
            *(float4*)(Og + (size_t)r0 * HS + cg * 8 + 4)       = make_float4(rlo[4], rlo[5], rlo[6], rlo[7]);
            *(float4*)(Og + (size_t)(r0 + 1) * HS + cg * 8)     = make_float4(rhi[0], rhi[1], rhi[2], rhi[3]);
            *(float4*)(Og + (size_t)(r0 + 1) * HS + cg * 8 + 4) = make_float4(rhi[4], rhi[5], rhi[6], rhi[7]);
        }
    }
}

extern "C" void kernel_launch(void* const* d_in, const int* in_sizes, int n_in,
                              void* d_out, int out_size)
{
    (void)in_sizes; (void)n_in; (void)out_size;
    const float* ix = (const float*)d_in[0];
    const float* Wk = (const float*)d_in[1];
    const float* Wq = (const float*)d_in[2];
    const float* Wv = (const float*)d_in[3];
    float* out = (float*)d_out;

    const int smem_bytes = (HS * SQT + 2 * FBN * SKV + FBN * SPT) * (int)sizeof(float);
    cudaFuncSetAttribute(flash_kernel,
                         cudaFuncAttributeMaxDynamicSharedMemorySize, smem_bytes);

    dim3 pgrid(MROWS / PBM, 3);
    proj_kernel<<<pgrid, 256>>>(ix, Wk, Wq, Wv);
    flash_kernel<<<BATCH * (NSEQ / FBM), 128, smem_bytes>>>(out);
}